// round 2
// baseline (speedup 1.0000x reference)
#include <cuda_runtime.h>
#include <cstdint>

// ---------------------------------------------------------------------------
// Fused SSIM(11x11 gaussian, separable) + Charbonnier + MSE loss.
// Input: pred, target  (16,3,512,512) fp32. Output: same shape fp32.
//
// One CTA computes a 32x32 output tile of one (n,c) plane:
//   1. load 42x42 halo tile of (pred,target) into SMEM as float2 (zero-pad OOB)
//   2. horizontal 11-tap pass for 5 quantities (p, t, p^2, t^2, p*t)
//   3. vertical 11-tap pass + elementwise loss
// ---------------------------------------------------------------------------

#define WIN   11
#define RAD   5
#define TX    32
#define TY    32
#define HX    (TX + 2*RAD)   // 42
#define HY    (TY + 2*RAD)   // 42
#define IMG_H 512
#define IMG_W 512
#define NTHREADS 256

// Normalized gaussian weights, sigma=1.5, window=11 (symmetric).
__constant__ float c_w[WIN] = {
    0.00102838f, 0.00759876f, 0.03600077f, 0.10936069f, 0.21300553f,
    0.26601172f,
    0.21300553f, 0.10936069f, 0.03600077f, 0.00759876f, 0.00102838f
};

__global__ __launch_bounds__(NTHREADS)
void ssim_charb_mse_kernel(const float* __restrict__ pred,
                           const float* __restrict__ targ,
                           float* __restrict__ out)
{
    // SMEM: raw halo tile (float2 {p,t}) + horizontal-pass intermediates
    __shared__ float2 s_raw[HY][HX];      // 42*42*8  = 14112 B
    __shared__ float4 s_h4[HY][TX];       // 42*32*16 = 21504 B  (mp,mt,mpp,mtt)
    __shared__ float  s_h1[HY][TX];       // 42*32*4  =  5376 B  (mpt)

    const int plane = blockIdx.z;                 // (n*C + c), 0..47
    const int x0 = blockIdx.x * TX;
    const int y0 = blockIdx.y * TY;
    const size_t pbase = (size_t)plane * IMG_H * IMG_W;
    const float* __restrict__ p = pred + pbase;
    const float* __restrict__ t = targ + pbase;
    float* __restrict__ o = out + pbase;

    const int tid = threadIdx.x;

    // ---- 1. cooperative load of 42x42 halo tile, zero-padded ----
    #pragma unroll
    for (int idx = tid; idx < HY * HX; idx += NTHREADS) {
        const int r = idx / HX;
        const int c = idx - r * HX;
        const int gy = y0 + r - RAD;
        const int gx = x0 + c - RAD;
        float2 v = make_float2(0.f, 0.f);
        if ((unsigned)gy < (unsigned)IMG_H && (unsigned)gx < (unsigned)IMG_W) {
            const int g = gy * IMG_W + gx;
            v.x = p[g];
            v.y = t[g];
        }
        s_raw[r][c] = v;
    }
    __syncthreads();

    // ---- 2. horizontal 11-tap pass: 42 rows x 32 cols ----
    #pragma unroll
    for (int idx = tid; idx < HY * TX; idx += NTHREADS) {
        const int r = idx >> 5;          // / 32
        const int c = idx & 31;          // % 32
        float mp = 0.f, mt = 0.f, mpp = 0.f, mtt = 0.f, mpt = 0.f;
        #pragma unroll
        for (int i = 0; i < WIN; ++i) {
            const float2 v = s_raw[r][c + i];
            const float w = c_w[i];
            const float px = v.x, tx = v.y;
            mp  += w * px;
            mt  += w * tx;
            mpp += w * (px * px);
            mtt += w * (tx * tx);
            mpt += w * (px * tx);
        }
        s_h4[r][c] = make_float4(mp, mt, mpp, mtt);
        s_h1[r][c] = mpt;
    }
    __syncthreads();

    // ---- 3. vertical 11-tap pass + loss, 32x32 outputs ----
    const float C1 = 0.0001f;       // (0.01)^2
    const float C2 = 0.0009f;       // (0.03)^2
    const float EPS2 = 1e-12f;      // (1e-6)^2

    #pragma unroll
    for (int idx = tid; idx < TY * TX; idx += NTHREADS) {
        const int r = idx >> 5;
        const int c = idx & 31;
        float mu_x = 0.f, mu_y = 0.f, sxx = 0.f, syy = 0.f, sxy = 0.f;
        #pragma unroll
        for (int j = 0; j < WIN; ++j) {
            const float4 v = s_h4[r + j][c];
            const float w = c_w[j];
            mu_x += w * v.x;
            mu_y += w * v.y;
            sxx  += w * v.z;
            syy  += w * v.w;
            sxy  += w * s_h1[r + j][c];
        }
        // moments -> (co)variance
        sxx = sxx - mu_x * mu_x;
        syy = syy - mu_y * mu_y;
        sxy = sxy - mu_x * mu_y;

        const float A1 = 2.f * mu_x * mu_y + C1;
        const float A2 = 2.f * sxy + C2;
        const float B1 = mu_x * mu_x + mu_y * mu_y + C1;
        const float B2 = sxx + syy + C2;
        const float ssim = (A1 / B1) * (A2 / B2);

        const float2 ct = s_raw[r + RAD][c + RAD];
        const float diff = ct.x - ct.y;
        const float d2 = diff * diff;
        const float charb = sqrtf(d2 + EPS2);
        const float loss = 0.3f * charb + 0.1f * (d2 * 20.f) + 0.6f * (1.f - ssim);

        o[(y0 + r) * IMG_W + (x0 + c)] = loss;
    }
}

extern "C" void kernel_launch(void* const* d_in, const int* in_sizes, int n_in,
                              void* d_out, int out_size)
{
    const float* pred = (const float*)d_in[0];
    const float* targ = (const float*)d_in[1];
    float* out = (float*)d_out;

    const int planes = out_size / (IMG_H * IMG_W);   // 16*3 = 48
    dim3 grid(IMG_W / TX, IMG_H / TY, planes);       // 16,16,48
    dim3 block(NTHREADS);
    ssim_charb_mse_kernel<<<grid, block>>>(pred, targ, out);
}

// round 3
// speedup vs baseline: 1.2153x; 1.2153x over previous
#include <cuda_runtime.h>
#include <cstdint>

// ---------------------------------------------------------------------------
// Fused SSIM(11x11 gaussian, separable) + Charbonnier + MSE loss.
// Register-blocked separable convolution: every smem value is loaded once and
// accumulated into up to 4 register accumulators (4-wide col/row blocking),
// cutting LDS traffic ~2.7x vs the naive per-tap re-read version.
// ---------------------------------------------------------------------------

#define WIN   11
#define RAD   5
#define TX    32
#define TY    32
#define HX    (TX + 2*RAD)   // 42
#define HY    (TY + 2*RAD)   // 42
#define IMG_H 512
#define IMG_W 512
#define NTHREADS 256
#define CG    4                       // columns per horizontal task
#define NHTASK (HY * (TX / CG))       // 42*8 = 336 horizontal tasks
#define RG    4                       // rows per vertical thread (32/8)

// Normalized gaussian weights, sigma=1.5, window=11 (symmetric).
__constant__ float c_w[WIN] = {
    0.00102838f, 0.00759876f, 0.03600077f, 0.10936069f, 0.21300553f,
    0.26601172f,
    0.21300553f, 0.10936069f, 0.03600077f, 0.00759876f, 0.00102838f
};

__global__ __launch_bounds__(NTHREADS)
void ssim_charb_mse_kernel(const float* __restrict__ pred,
                           const float* __restrict__ targ,
                           float* __restrict__ out)
{
    __shared__ float2 s_raw[HY][HX];      // 14112 B  {p,t}
    __shared__ float4 s_h4[HY][TX];       // 21504 B  (mp,mt,mpp,mtt)
    __shared__ float  s_h1[HY][TX];       //  5376 B  (mpt)

    const int plane = blockIdx.z;
    const int x0 = blockIdx.x * TX;
    const int y0 = blockIdx.y * TY;
    const size_t pbase = (size_t)plane * IMG_H * IMG_W;
    const float* __restrict__ p = pred + pbase;
    const float* __restrict__ t = targ + pbase;
    float* __restrict__ o = out + pbase;

    const int tid = threadIdx.x;

    // ---- 1. cooperative load of 42x42 halo tile, zero-padded ----
    #pragma unroll
    for (int idx = tid; idx < HY * HX; idx += NTHREADS) {
        const int r = idx / HX;
        const int c = idx - r * HX;
        const int gy = y0 + r - RAD;
        const int gx = x0 + c - RAD;
        float2 v = make_float2(0.f, 0.f);
        if ((unsigned)gy < (unsigned)IMG_H && (unsigned)gx < (unsigned)IMG_W) {
            const int g = gy * IMG_W + gx;
            v.x = p[g];
            v.y = t[g];
        }
        s_raw[r][c] = v;
    }
    __syncthreads();

    // ---- 2. horizontal pass, register-blocked: each task = 1 row x 4 cols ----
    // Reads 14 float2 per task instead of 4*11; products computed once per input.
    for (int idx = tid; idx < NHTASK; idx += NTHREADS) {
        const int g  = idx & (TX / CG - 1);   // col group 0..7
        const int r  = idx >> 3;              // row 0..41
        const int c0 = g * CG;

        float mp[CG], mt[CG], mpp[CG], mtt[CG], mpt[CG];
        #pragma unroll
        for (int k = 0; k < CG; ++k) { mp[k]=0.f; mt[k]=0.f; mpp[k]=0.f; mtt[k]=0.f; mpt[k]=0.f; }

        #pragma unroll
        for (int i = 0; i < CG + WIN - 1; ++i) {       // 14 input columns
            const float2 v = s_raw[r][c0 + i];
            const float px = v.x, tx = v.y;
            const float pp = px * px;
            const float tt = tx * tx;
            const float pt = px * tx;
            #pragma unroll
            for (int k = 0; k < CG; ++k) {
                const int tap = i - k;
                if (tap >= 0 && tap < WIN) {
                    const float w = c_w[tap];          // compile-time index -> imm
                    mp[k]  += w * px;
                    mt[k]  += w * tx;
                    mpp[k] += w * pp;
                    mtt[k] += w * tt;
                    mpt[k] += w * pt;
                }
            }
        }
        #pragma unroll
        for (int k = 0; k < CG; ++k) {
            s_h4[r][c0 + k] = make_float4(mp[k], mt[k], mpp[k], mtt[k]);
            s_h1[r][c0 + k] = mpt[k];
        }
    }
    __syncthreads();

    // ---- 3. vertical pass, register-blocked: each thread = 4-row column strip ----
    const int c  = tid & 31;        // column 0..31
    const int rg = tid >> 5;        // row group 0..7
    const int r0 = rg * RG;

    float vmx[RG], vmy[RG], vxx[RG], vyy[RG], vxy[RG];
    #pragma unroll
    for (int k = 0; k < RG; ++k) { vmx[k]=0.f; vmy[k]=0.f; vxx[k]=0.f; vyy[k]=0.f; vxy[k]=0.f; }

    #pragma unroll
    for (int j = 0; j < RG + WIN - 1; ++j) {           // 14 h-rows
        const float4 h  = s_h4[r0 + j][c];
        const float  h1 = s_h1[r0 + j][c];
        #pragma unroll
        for (int k = 0; k < RG; ++k) {
            const int tap = j - k;
            if (tap >= 0 && tap < WIN) {
                const float w = c_w[tap];
                vmx[k] += w * h.x;
                vmy[k] += w * h.y;
                vxx[k] += w * h.z;
                vyy[k] += w * h.w;
                vxy[k] += w * h1;
            }
        }
    }

    const float C1 = 0.0001f;       // (0.01)^2
    const float C2 = 0.0009f;       // (0.03)^2
    const float EPS2 = 1e-12f;      // (1e-6)^2

    #pragma unroll
    for (int k = 0; k < RG; ++k) {
        const float mu_x = vmx[k], mu_y = vmy[k];
        const float sxx = vxx[k] - mu_x * mu_x;
        const float syy = vyy[k] - mu_y * mu_y;
        const float sxy = vxy[k] - mu_x * mu_y;

        const float A1 = 2.f * mu_x * mu_y + C1;
        const float A2 = 2.f * sxy + C2;
        const float B1 = mu_x * mu_x + mu_y * mu_y + C1;
        const float B2 = sxx + syy + C2;
        const float ssim = __fdividef(A1 * A2, B1 * B2);

        const float2 ct = s_raw[r0 + k + RAD][c + RAD];
        const float diff = ct.x - ct.y;
        const float d2 = diff * diff;
        const float charb = sqrtf(d2 + EPS2);
        const float loss = 0.3f * charb + 2.0f * d2 + 0.6f * (1.f - ssim);

        o[(y0 + r0 + k) * IMG_W + (x0 + c)] = loss;
    }
}

extern "C" void kernel_launch(void* const* d_in, const int* in_sizes, int n_in,
                              void* d_out, int out_size)
{
    const float* pred = (const float*)d_in[0];
    const float* targ = (const float*)d_in[1];
    float* out = (float*)d_out;

    const int planes = out_size / (IMG_H * IMG_W);   // 16*3 = 48
    dim3 grid(IMG_W / TX, IMG_H / TY, planes);       // 16,16,48
    dim3 block(NTHREADS);
    ssim_charb_mse_kernel<<<grid, block>>>(pred, targ, out);
}

// round 4
// speedup vs baseline: 1.4537x; 1.1961x over previous
#include <cuda_runtime.h>
#include <cstdint>

// ---------------------------------------------------------------------------
// Fused SSIM(11x11 gaussian) + Charbonnier + MSE loss — sum/diff reformulation.
//
// s = p + t, d = p - t. Only FOUR gaussian-filtered channels needed:
//   Es = G(s), Ed = G(d), Es2 = G(s^2), Ed2 = G(d^2)
//   A1 = (Es^2 - Ed^2)/2 + C1            (= 2 mu_x mu_y + C1)
//   B1 = (Es^2 + Ed^2)/2 + C1            (= mu_x^2 + mu_y^2 + C1)
//   A2 = ((Es2-Ed2) - (Es^2-Ed^2))/2 + C2 (= 2 sigma_xy + C2)
//   B2 = ((Es2+Ed2) - (Es^2+Ed^2))/2 + C2 (= sxx + syy + C2)
// Charbonnier/MSE use d at the center pixel.
//
// All smem arrays are scalar with odd-ish row strides chosen so every LDS/STS
// in both conv passes is bank-conflict-free (1 wavefront per warp inst).
// ---------------------------------------------------------------------------

#define WIN   11
#define RAD   5
#define TX    32
#define TY    32
#define HX    42            // TX + 2*RAD
#define HY    42
#define SR    43            // raw row stride (floats): (11r+8g+i) distinct mod 32
#define SH    33            // intermediate row stride: (r+8g) distinct mod 32
#define IMG_H 512
#define IMG_W 512
#define NTHREADS 256
#define CG    8             // cols per horizontal task (42*4 = 168 tasks)
#define RG    4             // rows per vertical thread

__constant__ float c_w[WIN] = {
    0.00102838f, 0.00759876f, 0.03600077f, 0.10936069f, 0.21300553f,
    0.26601172f,
    0.21300553f, 0.10936069f, 0.03600077f, 0.00759876f, 0.00102838f
};

__global__ __launch_bounds__(NTHREADS)
void ssim_charb_mse_kernel(const float* __restrict__ pred,
                           const float* __restrict__ targ,
                           float* __restrict__ out)
{
    __shared__ float s_s[HY * SR];    // 7224 B  sum  = p+t
    __shared__ float s_d[HY * SR];    // 7224 B  diff = p-t
    __shared__ float h_s [HY * SH];   // 5544 B  horiz G(s)
    __shared__ float h_d [HY * SH];   //          horiz G(d)
    __shared__ float h_s2[HY * SH];   //          horiz G(s^2)
    __shared__ float h_d2[HY * SH];   //          horiz G(d^2)

    const int plane = blockIdx.z;
    const int x0 = blockIdx.x * TX;
    const int y0 = blockIdx.y * TY;
    const size_t pbase = (size_t)plane * IMG_H * IMG_W;
    const float* __restrict__ p = pred + pbase;
    const float* __restrict__ t = targ + pbase;
    float* __restrict__ o = out + pbase;

    const int tid = threadIdx.x;

    // ---- 1. halo load: compute s,d on the fly, zero-pad OOB ----
    #pragma unroll
    for (int idx = tid; idx < HY * HX; idx += NTHREADS) {
        const int r = idx / HX;
        const int c = idx - r * HX;
        const int gy = y0 + r - RAD;
        const int gx = x0 + c - RAD;
        float sv = 0.f, dv = 0.f;
        if ((unsigned)gy < (unsigned)IMG_H && (unsigned)gx < (unsigned)IMG_W) {
            const int g = gy * IMG_W + gx;
            const float pv = p[g];
            const float tv = t[g];
            sv = pv + tv;
            dv = pv - tv;
        }
        s_s[r * SR + c] = sv;
        s_d[r * SR + c] = dv;
    }
    __syncthreads();

    // ---- 2. horizontal pass: 168 tasks, each 1 row x 8 cols, 4 channels ----
    if (tid < HY * (TX / CG)) {           // 42 * 4 = 168
        const int g  = tid & 3;           // col group 0..3
        const int r  = tid >> 2;          // row 0..41
        const int c0 = g * CG;
        const int rb = r * SR + c0;

        float ms[CG], md[CG], ms2[CG], md2[CG];
        #pragma unroll
        for (int k = 0; k < CG; ++k) { ms[k]=0.f; md[k]=0.f; ms2[k]=0.f; md2[k]=0.f; }

        #pragma unroll
        for (int i = 0; i < CG + WIN - 1; ++i) {     // 18 input cols
            const float sv = s_s[rb + i];
            const float dv = s_d[rb + i];
            const float s2 = sv * sv;
            const float d2 = dv * dv;
            #pragma unroll
            for (int k = 0; k < CG; ++k) {
                const int tap = i - k;
                if (tap >= 0 && tap < WIN) {
                    const float w = c_w[tap];        // compile-time -> imm FFMA
                    ms[k]  += w * sv;
                    md[k]  += w * dv;
                    ms2[k] += w * s2;
                    md2[k] += w * d2;
                }
            }
        }
        const int hb = r * SH + c0;
        #pragma unroll
        for (int k = 0; k < CG; ++k) {
            h_s [hb + k] = ms[k];
            h_d [hb + k] = md[k];
            h_s2[hb + k] = ms2[k];
            h_d2[hb + k] = md2[k];
        }
    }
    __syncthreads();

    // ---- 3. vertical pass + loss: thread = 4-row column strip ----
    const int c  = tid & 31;
    const int rg = tid >> 5;
    const int r0 = rg * RG;

    float Es[RG], Ed[RG], Es2[RG], Ed2[RG];
    #pragma unroll
    for (int k = 0; k < RG; ++k) { Es[k]=0.f; Ed[k]=0.f; Es2[k]=0.f; Ed2[k]=0.f; }

    #pragma unroll
    for (int j = 0; j < RG + WIN - 1; ++j) {         // 14 h-rows
        const int hb = (r0 + j) * SH + c;
        const float vs  = h_s [hb];
        const float vd  = h_d [hb];
        const float vs2 = h_s2[hb];
        const float vd2 = h_d2[hb];
        #pragma unroll
        for (int k = 0; k < RG; ++k) {
            const int tap = j - k;
            if (tap >= 0 && tap < WIN) {
                const float w = c_w[tap];
                Es[k]  += w * vs;
                Ed[k]  += w * vd;
                Es2[k] += w * vs2;
                Ed2[k] += w * vd2;
            }
        }
    }

    const float C1 = 0.0001f;       // (0.01)^2
    const float C2 = 0.0009f;       // (0.03)^2
    const float EPS2 = 1e-12f;      // (1e-6)^2

    #pragma unroll
    for (int k = 0; k < RG; ++k) {
        const float mus2 = Es[k] * Es[k];    // (mu_x+mu_y)^2
        const float mud2 = Ed[k] * Ed[k];    // (mu_x-mu_y)^2
        const float dif  = 0.5f * (mus2 - mud2);   // 2 mu_x mu_y
        const float sum  = 0.5f * (mus2 + mud2);   // mu_x^2 + mu_y^2

        const float A1 = dif + C1;
        const float B1 = sum + C1;
        const float A2 = 0.5f * (Es2[k] - Ed2[k]) - dif + C2;   // 2 sigma_xy + C2
        const float B2 = 0.5f * (Es2[k] + Ed2[k]) - sum + C2;   // sxx+syy + C2
        const float ssim = __fdividef(A1 * A2, B1 * B2);

        const float dcen = s_d[(r0 + k + RAD) * SR + (c + RAD)];
        const float d2c  = dcen * dcen;
        const float charb = sqrtf(d2c + EPS2);
        const float loss = 0.3f * charb + 2.0f * d2c + 0.6f * (1.f - ssim);

        o[(y0 + r0 + k) * IMG_W + (x0 + c)] = loss;
    }
}

extern "C" void kernel_launch(void* const* d_in, const int* in_sizes, int n_in,
                              void* d_out, int out_size)
{
    const float* pred = (const float*)d_in[0];
    const float* targ = (const float*)d_in[1];
    float* out = (float*)d_out;

    const int planes = out_size / (IMG_H * IMG_W);   // 48
    dim3 grid(IMG_W / TX, IMG_H / TY, planes);       // 16,16,48
    dim3 block(NTHREADS);
    ssim_charb_mse_kernel<<<grid, block>>>(pred, targ, out);
}

// round 5
// speedup vs baseline: 1.8476x; 1.2710x over previous
#include <cuda_runtime.h>
#include <cstdint>

// ---------------------------------------------------------------------------
// Fused SSIM(11x11 gaussian) + Charbonnier + MSE — sum/diff + packed f32x2.
//
// s=p+t, d=p-t. Channels G(s),G(d),G(s^2),G(d^2) reconstruct all SSIM terms.
// The two channel pairs travel as packed f32x2 (64-bit regs): conv taps are
// fma.rn.f32x2, smem traffic is LDS.64/STS.64 -> instruction stream ~halved
// vs scalar (kernel was issue-bound at 89.6%).
// ---------------------------------------------------------------------------

#define WIN   11
#define RAD   5
#define TX    32
#define TY    32
#define HX    42
#define HY    42
#define SR2   43            // raw row stride in 8B units (odd -> conflict-free)
#define SH2   33            // intermediate row stride in 8B units
#define IMG_H 512
#define IMG_W 512
#define NTHREADS 256
#define CG    8             // cols per horizontal task: 42*4 = 168 tasks
#define RG    8             // rows per vertical thread: 32*4 = 128 tasks

typedef unsigned long long ull;

__device__ __forceinline__ ull pk(float a, float b) {
    return ((ull)__float_as_uint(b) << 32) | (ull)__float_as_uint(a);
}
__device__ __forceinline__ float flo(ull v) { return __uint_as_float((unsigned)v); }
__device__ __forceinline__ float fhi(ull v) { return __uint_as_float((unsigned)(v >> 32)); }

__device__ __forceinline__ ull fma2(ull a, ull b, ull c) {
    ull d;
    asm("fma.rn.f32x2 %0, %1, %2, %3;" : "=l"(d) : "l"(a), "l"(b), "l"(c));
    return d;
}
__device__ __forceinline__ ull mul2(ull a, ull b) {
    ull d;
    asm("mul.rn.f32x2 %0, %1, %2;" : "=l"(d) : "l"(a), "l"(b));
    return d;
}
__device__ __forceinline__ float sqrt_approx(float x) {
    float r;
    asm("sqrt.approx.f32 %0, %1;" : "=f"(r) : "f"(x));
    return r;
}

// gaussian weights (sigma=1.5, win=11), compile-time foldable
__device__ __forceinline__ float cw(int i) {
    constexpr float W[WIN] = {
        0.00102838f, 0.00759876f, 0.03600077f, 0.10936069f, 0.21300553f,
        0.26601172f,
        0.21300553f, 0.10936069f, 0.03600077f, 0.00759876f, 0.00102838f };
    return W[i];
}

__global__ __launch_bounds__(NTHREADS)
void ssim_charb_mse_kernel(const float* __restrict__ pred,
                           const float* __restrict__ targ,
                           float* __restrict__ out)
{
    __shared__ ull s_raw[HY * SR2];   // 14448 B : packed (s, d)
    __shared__ ull h_a[HY * SH2];     // 11088 B : packed (G_h(s),  G_h(d))
    __shared__ ull h_b[HY * SH2];     // 11088 B : packed (G_h(s^2),G_h(d^2))

    const int plane = blockIdx.z;
    const int x0 = blockIdx.x * TX;
    const int y0 = blockIdx.y * TY;
    const size_t pbase = (size_t)plane * IMG_H * IMG_W;
    const float* __restrict__ p = pred + pbase;
    const float* __restrict__ t = targ + pbase;
    float* __restrict__ o = out + pbase;

    const int tid = threadIdx.x;

    // ---- 1. halo load: pack (s,d), interior CTAs skip bounds checks ----
    const bool interior = (x0 >= RAD) & (x0 + TX + RAD <= IMG_W) &
                          (y0 >= RAD) & (y0 + TY + RAD <= IMG_H);
    if (interior) {
        const int gb = (y0 - RAD) * IMG_W + (x0 - RAD);
        #pragma unroll
        for (int idx = tid; idx < HY * HX; idx += NTHREADS) {
            const int r = idx / HX;
            const int c = idx - r * HX;
            const int g = gb + r * IMG_W + c;
            const float pv = p[g];
            const float tv = t[g];
            s_raw[r * SR2 + c] = pk(pv + tv, pv - tv);
        }
    } else {
        #pragma unroll
        for (int idx = tid; idx < HY * HX; idx += NTHREADS) {
            const int r = idx / HX;
            const int c = idx - r * HX;
            const int gy = y0 + r - RAD;
            const int gx = x0 + c - RAD;
            float sv = 0.f, dv = 0.f;
            if ((unsigned)gy < (unsigned)IMG_H && (unsigned)gx < (unsigned)IMG_W) {
                const int g = gy * IMG_W + gx;
                const float pv = p[g];
                const float tv = t[g];
                sv = pv + tv;
                dv = pv - tv;
            }
            s_raw[r * SR2 + c] = pk(sv, dv);
        }
    }
    __syncthreads();

    // ---- 2. horizontal pass: 168 tasks (lane <-> row), 2 packed channels ----
    if (tid < HY * (TX / CG)) {                // 42*4 = 168
        const int g  = tid / HY;               // col group 0..3
        const int r  = tid - g * HY;           // row 0..41 (consecutive in lane)
        const int c0 = g * CG;
        const int rb = r * SR2 + c0;

        ull m1[CG], m2[CG];
        #pragma unroll
        for (int k = 0; k < CG; ++k) { m1[k] = 0ULL; m2[k] = 0ULL; }

        #pragma unroll
        for (int i = 0; i < CG + WIN - 1; ++i) {          // 18 inputs
            const ull v  = s_raw[rb + i];                 // (s, d)
            const ull v2 = mul2(v, v);                    // (s^2, d^2)
            #pragma unroll
            for (int k = 0; k < CG; ++k) {
                const int tap = i - k;
                if (tap >= 0 && tap < WIN) {
                    const ull w = pk(cw(tap), cw(tap));   // compile-time const
                    m1[k] = fma2(w, v,  m1[k]);
                    m2[k] = fma2(w, v2, m2[k]);
                }
            }
        }
        const int hb = r * SH2 + c0;
        #pragma unroll
        for (int k = 0; k < CG; ++k) {
            h_a[hb + k] = m1[k];
            h_b[hb + k] = m2[k];
        }
    }
    __syncthreads();

    // ---- 3. vertical pass + loss: 128 tasks, 8-row column strips ----
    if (tid < TX * (TY / RG)) {                // 32*4 = 128
        const int c  = tid & 31;
        const int rg = tid >> 5;               // strip 0..3
        const int r0 = rg * RG;

        ull E1[RG], E2[RG];
        #pragma unroll
        for (int k = 0; k < RG; ++k) { E1[k] = 0ULL; E2[k] = 0ULL; }

        #pragma unroll
        for (int j = 0; j < RG + WIN - 1; ++j) {          // 18 h-rows
            const int hb = (r0 + j) * SH2 + c;
            const ull va = h_a[hb];
            const ull vb = h_b[hb];
            #pragma unroll
            for (int k = 0; k < RG; ++k) {
                const int tap = j - k;
                if (tap >= 0 && tap < WIN) {
                    const ull w = pk(cw(tap), cw(tap));
                    E1[k] = fma2(w, va, E1[k]);
                    E2[k] = fma2(w, vb, E2[k]);
                }
            }
        }

        const float C1 = 0.0001f;       // (0.01)^2
        const float C2 = 0.0009f;       // (0.03)^2
        const float EPS2 = 1e-12f;      // (1e-6)^2

        #pragma unroll
        for (int k = 0; k < RG; ++k) {
            const float Es  = flo(E1[k]), Ed  = fhi(E1[k]);
            const float Es2 = flo(E2[k]), Ed2 = fhi(E2[k]);

            const float mus2 = Es * Es;              // (mx+my)^2
            const float mud2 = Ed * Ed;              // (mx-my)^2
            const float dif  = 0.5f * (mus2 - mud2); // 2 mx my
            const float sum  = 0.5f * (mus2 + mud2); // mx^2 + my^2

            const float A1 = dif + C1;
            const float B1 = sum + C1;
            const float A2 = 0.5f * (Es2 - Ed2) - dif + C2;
            const float B2 = 0.5f * (Es2 + Ed2) - sum + C2;
            const float ssim = __fdividef(A1 * A2, B1 * B2);

            const float dcen = fhi(s_raw[(r0 + k + RAD) * SR2 + (c + RAD)]);
            const float d2c  = dcen * dcen;
            const float charb = sqrt_approx(d2c + EPS2);
            const float loss = 0.3f * charb + 2.0f * d2c + 0.6f * (1.f - ssim);

            o[(y0 + r0 + k) * IMG_W + (x0 + c)] = loss;
        }
    }
}

extern "C" void kernel_launch(void* const* d_in, const int* in_sizes, int n_in,
                              void* d_out, int out_size)
{
    const float* pred = (const float*)d_in[0];
    const float* targ = (const float*)d_in[1];
    float* out = (float*)d_out;

    const int planes = out_size / (IMG_H * IMG_W);   // 48
    dim3 grid(IMG_W / TX, IMG_H / TY, planes);       // 16,16,48
    dim3 block(NTHREADS);
    ssim_charb_mse_kernel<<<grid, block>>>(pred, targ, out);
}

// round 6
// speedup vs baseline: 1.9420x; 1.0511x over previous
#include <cuda_runtime.h>
#include <cstdint>

// ---------------------------------------------------------------------------
// Fused SSIM(11x11 gaussian) + Charbonnier + MSE — sum/diff + packed f32x2.
//
// s=p+t, d=p-t. Channels G(s),G(d),G(s^2),G(d^2) reconstruct all SSIM terms.
// The two channel pairs travel as packed f32x2 (64-bit regs): conv taps are
// fma.rn.f32x2, smem traffic is LDS.64/STS.64 -> instruction stream ~halved
// vs scalar (kernel was issue-bound at 89.6%).
// ---------------------------------------------------------------------------

#define WIN   11
#define RAD   5
#define TX    32
#define TY    32
#define HX    42
#define HY    42
#define SR2   43            // raw row stride in 8B units (odd -> conflict-free)
#define SH2   33            // intermediate row stride in 8B units
#define IMG_H 512
#define IMG_W 512
#define NTHREADS 256
#define CG    8             // cols per horizontal task: 42*4 = 168 tasks
#define RG    8             // rows per vertical thread: 32*4 = 128 tasks

typedef unsigned long long ull;

__device__ __forceinline__ ull pk(float a, float b) {
    return ((ull)__float_as_uint(b) << 32) | (ull)__float_as_uint(a);
}
__device__ __forceinline__ float flo(ull v) { return __uint_as_float((unsigned)v); }
__device__ __forceinline__ float fhi(ull v) { return __uint_as_float((unsigned)(v >> 32)); }

__device__ __forceinline__ ull fma2(ull a, ull b, ull c) {
    ull d;
    asm("fma.rn.f32x2 %0, %1, %2, %3;" : "=l"(d) : "l"(a), "l"(b), "l"(c));
    return d;
}
__device__ __forceinline__ ull mul2(ull a, ull b) {
    ull d;
    asm("mul.rn.f32x2 %0, %1, %2;" : "=l"(d) : "l"(a), "l"(b));
    return d;
}
__device__ __forceinline__ float sqrt_approx(float x) {
    float r;
    asm("sqrt.approx.f32 %0, %1;" : "=f"(r) : "f"(x));
    return r;
}

// gaussian weights (sigma=1.5, win=11), compile-time foldable
__device__ __forceinline__ float cw(int i) {
    constexpr float W[WIN] = {
        0.00102838f, 0.00759876f, 0.03600077f, 0.10936069f, 0.21300553f,
        0.26601172f,
        0.21300553f, 0.10936069f, 0.03600077f, 0.00759876f, 0.00102838f };
    return W[i];
}

__global__ __launch_bounds__(NTHREADS)
void ssim_charb_mse_kernel(const float* __restrict__ pred,
                           const float* __restrict__ targ,
                           float* __restrict__ out)
{
    __shared__ ull s_raw[HY * SR2];   // 14448 B : packed (s, d)
    __shared__ ull h_a[HY * SH2];     // 11088 B : packed (G_h(s),  G_h(d))
    __shared__ ull h_b[HY * SH2];     // 11088 B : packed (G_h(s^2),G_h(d^2))

    const int plane = blockIdx.z;
    const int x0 = blockIdx.x * TX;
    const int y0 = blockIdx.y * TY;
    const size_t pbase = (size_t)plane * IMG_H * IMG_W;
    const float* __restrict__ p = pred + pbase;
    const float* __restrict__ t = targ + pbase;
    float* __restrict__ o = out + pbase;

    const int tid = threadIdx.x;

    // ---- 1. halo load: pack (s,d), interior CTAs skip bounds checks ----
    const bool interior = (x0 >= RAD) & (x0 + TX + RAD <= IMG_W) &
                          (y0 >= RAD) & (y0 + TY + RAD <= IMG_H);
    if (interior) {
        const int gb = (y0 - RAD) * IMG_W + (x0 - RAD);
        #pragma unroll
        for (int idx = tid; idx < HY * HX; idx += NTHREADS) {
            const int r = idx / HX;
            const int c = idx - r * HX;
            const int g = gb + r * IMG_W + c;
            const float pv = p[g];
            const float tv = t[g];
            s_raw[r * SR2 + c] = pk(pv + tv, pv - tv);
        }
    } else {
        #pragma unroll
        for (int idx = tid; idx < HY * HX; idx += NTHREADS) {
            const int r = idx / HX;
            const int c = idx - r * HX;
            const int gy = y0 + r - RAD;
            const int gx = x0 + c - RAD;
            float sv = 0.f, dv = 0.f;
            if ((unsigned)gy < (unsigned)IMG_H && (unsigned)gx < (unsigned)IMG_W) {
                const int g = gy * IMG_W + gx;
                const float pv = p[g];
                const float tv = t[g];
                sv = pv + tv;
                dv = pv - tv;
            }
            s_raw[r * SR2 + c] = pk(sv, dv);
        }
    }
    __syncthreads();

    // ---- 2. horizontal pass: 168 tasks (lane <-> row), 2 packed channels ----
    if (tid < HY * (TX / CG)) {                // 42*4 = 168
        const int g  = tid / HY;               // col group 0..3
        const int r  = tid - g * HY;           // row 0..41 (consecutive in lane)
        const int c0 = g * CG;
        const int rb = r * SR2 + c0;

        ull m1[CG], m2[CG];
        #pragma unroll
        for (int k = 0; k < CG; ++k) { m1[k] = 0ULL; m2[k] = 0ULL; }

        #pragma unroll
        for (int i = 0; i < CG + WIN - 1; ++i) {          // 18 inputs
            const ull v  = s_raw[rb + i];                 // (s, d)
            const ull v2 = mul2(v, v);                    // (s^2, d^2)
            #pragma unroll
            for (int k = 0; k < CG; ++k) {
                const int tap = i - k;
                if (tap >= 0 && tap < WIN) {
                    const ull w = pk(cw(tap), cw(tap));   // compile-time const
                    m1[k] = fma2(w, v,  m1[k]);
                    m2[k] = fma2(w, v2, m2[k]);
                }
            }
        }
        const int hb = r * SH2 + c0;
        #pragma unroll
        for (int k = 0; k < CG; ++k) {
            h_a[hb + k] = m1[k];
            h_b[hb + k] = m2[k];
        }
    }
    __syncthreads();

    // ---- 3. vertical pass + loss: 128 tasks, 8-row column strips ----
    if (tid < TX * (TY / RG)) {                // 32*4 = 128
        const int c  = tid & 31;
        const int rg = tid >> 5;               // strip 0..3
        const int r0 = rg * RG;

        ull E1[RG], E2[RG];
        #pragma unroll
        for (int k = 0; k < RG; ++k) { E1[k] = 0ULL; E2[k] = 0ULL; }

        #pragma unroll
        for (int j = 0; j < RG + WIN - 1; ++j) {          // 18 h-rows
            const int hb = (r0 + j) * SH2 + c;
            const ull va = h_a[hb];
            const ull vb = h_b[hb];
            #pragma unroll
            for (int k = 0; k < RG; ++k) {
                const int tap = j - k;
                if (tap >= 0 && tap < WIN) {
                    const ull w = pk(cw(tap), cw(tap));
                    E1[k] = fma2(w, va, E1[k]);
                    E2[k] = fma2(w, vb, E2[k]);
                }
            }
        }

        const float C1 = 0.0001f;       // (0.01)^2
        const float C2 = 0.0009f;       // (0.03)^2
        const float EPS2 = 1e-12f;      // (1e-6)^2

        #pragma unroll
        for (int k = 0; k < RG; ++k) {
            const float Es  = flo(E1[k]), Ed  = fhi(E1[k]);
            const float Es2 = flo(E2[k]), Ed2 = fhi(E2[k]);

            const float mus2 = Es * Es;              // (mx+my)^2
            const float mud2 = Ed * Ed;              // (mx-my)^2
            const float dif  = 0.5f * (mus2 - mud2); // 2 mx my
            const float sum  = 0.5f * (mus2 + mud2); // mx^2 + my^2

            const float A1 = dif + C1;
            const float B1 = sum + C1;
            const float A2 = 0.5f * (Es2 - Ed2) - dif + C2;
            const float B2 = 0.5f * (Es2 + Ed2) - sum + C2;
            const float ssim = __fdividef(A1 * A2, B1 * B2);

            const float dcen = fhi(s_raw[(r0 + k + RAD) * SR2 + (c + RAD)]);
            const float d2c  = dcen * dcen;
            const float charb = sqrt_approx(d2c + EPS2);
            const float loss = 0.3f * charb + 2.0f * d2c + 0.6f * (1.f - ssim);

            o[(y0 + r0 + k) * IMG_W + (x0 + c)] = loss;
        }
    }
}

extern "C" void kernel_launch(void* const* d_in, const int* in_sizes, int n_in,
                              void* d_out, int out_size)
{
    const float* pred = (const float*)d_in[0];
    const float* targ = (const float*)d_in[1];
    float* out = (float*)d_out;

    const int planes = out_size / (IMG_H * IMG_W);   // 48
    dim3 grid(IMG_W / TX, IMG_H / TY, planes);       // 16,16,48
    dim3 block(NTHREADS);
    ssim_charb_mse_kernel<<<grid, block>>>(pred, targ, out);
}